// round 1
// baseline (speedup 1.0000x reference)
#include <cuda_runtime.h>
#include <math.h>
#include <stdint.h>

// Problem shape (fixed by the dataset): edge (16, 1, 1024, 1024) float32
#define BATCH 16
#define H 1024
#define W 1024
#define HW (H * W)          // 1048576 per batch
#define NQ 4                // 4 order statistics: lo_k, lo_k+1, hi_k, hi_k+1
#define TWO_PI_F 6.28318530717958647692f
#define STEP_F 0.78539816339744830962f   /* 2*pi/8 */
#define EPSV 1e-6f

// ---------------- device scratch (no cudaMalloc allowed) ----------------
__device__ unsigned g_hist[BATCH][NQ][2048];
__device__ unsigned g_prefix[BATCH][NQ];
__device__ int      g_rank[BATCH][NQ];
__device__ float    g_qval[BATCH][NQ];
__device__ float    g_xnorm[(size_t)BATCH * HW];   // used only if d_out lacks segment 3

__constant__ int c_dy[8] = {0, -1, -1, -1, 0, 1, 1, 1};
__constant__ int c_dx[8] = {1, 1, 0, -1, -1, -1, 0, 1};

// ---------------- key helpers: order-preserving float<->uint ----------------
__device__ __forceinline__ unsigned f2key(float f) {
    unsigned u = __float_as_uint(f);
    return (u & 0x80000000u) ? ~u : (u | 0x80000000u);
}
__device__ __forceinline__ float key2f(unsigned k) {
    unsigned u = (k & 0x80000000u) ? (k & 0x7fffffffu) : ~k;
    return __uint_as_float(u);
}

// ---------------- init: reset ranks/prefixes, zero hist ----------------
__global__ void k_init() {
    int i = blockIdx.x * blockDim.x + threadIdx.x;
    int total = BATCH * NQ * 2048;
    unsigned* h = &g_hist[0][0][0];
    for (int j = i; j < total; j += gridDim.x * blockDim.x) h[j] = 0u;
    if (i < BATCH * NQ) {
        int b = i / NQ, t = i % NQ;
        // ranks for quantile(0.02) and quantile(0.98) with n = HW:
        // pos = q*(n-1); floor = 20971 / 1027603, we need floor and floor+1
        const int ranks[NQ] = {20971, 20972, 1027603, 1027604};
        g_rank[b][t] = ranks[t];
        g_prefix[b][t] = 0u;
    }
}

// ---------------- radix-select histogram pass ----------------
// SHIFT/BITS select the digit; PBITS is the number of already-resolved top bits.
template <int SHIFT, int BITS, int PBITS>
__global__ void k_hist(const float* __restrict__ x) {
    constexpr int NB = 1 << BITS;
    constexpr int NT = (PBITS == 0) ? 1 : NQ;  // pass 1: single shared histogram
    __shared__ unsigned sh[NT][NB];
    __shared__ unsigned spref[NQ];
    int b = blockIdx.y;
    for (int i = threadIdx.x; i < NT * NB; i += blockDim.x) ((unsigned*)sh)[i] = 0u;
    if (threadIdx.x < NQ) spref[threadIdx.x] = g_prefix[b][threadIdx.x];
    __syncthreads();
    unsigned pref[NQ];
#pragma unroll
    for (int t = 0; t < NQ; t++) pref[t] = spref[t];

    const float4* xb = (const float4*)(x + (size_t)b * HW);
    const int nvec = HW / 4;  // 262144 — with grid (128, B) x 256 threads: exactly 8 iters/thread
    for (int i = blockIdx.x * blockDim.x + threadIdx.x; i < nvec; i += gridDim.x * blockDim.x) {
        float4 v = xb[i];
        float vs[4] = {v.x, v.y, v.z, v.w};
#pragma unroll
        for (int e = 0; e < 4; e++) {
            unsigned key = f2key(vs[e]);
            unsigned hi  = (PBITS == 0) ? 0u : (key >> (32 - (PBITS == 0 ? 1 : PBITS)));
            unsigned dig = (key >> SHIFT) & (NB - 1);
#pragma unroll
            for (int t = 0; t < NT; t++) {
                bool m = (PBITS == 0) || (hi == pref[t]);
                unsigned ball = __ballot_sync(0xffffffffu, m);
                if (m) {
                    unsigned same = __match_any_sync(ball, dig);
                    int leader = __ffs(same) - 1;
                    if ((int)(threadIdx.x & 31) == leader)
                        atomicAdd(&sh[t][dig], (unsigned)__popc(same));
                }
            }
        }
    }
    __syncthreads();
    for (int i = threadIdx.x; i < NT * NB; i += blockDim.x) {
        unsigned c = ((unsigned*)sh)[i];
        if (c) {
            int t = i >> BITS, d = i & (NB - 1);
            atomicAdd(&g_hist[b][t][d], c);
        }
    }
}

// ---------------- scan: locate digit containing each rank; zero hist ----------------
__global__ void k_scan(int bits, int first, int last) {
    int tid = threadIdx.x;  // launched with 64 threads, 1 block
    if (tid < BATCH * NQ) {
        int b = tid / NQ, t = tid % NQ;
        unsigned* h = g_hist[b][first ? 0 : t];
        int rank = g_rank[b][t];
        int nb = 1 << bits;
        int cum = 0, found = 0;
        unsigned pfx = g_prefix[b][t];
        for (int d = 0; d < nb; d++) {
            int c = (int)h[d];
            if (!found && cum + c > rank) {
                found = 1;
                pfx = (pfx << bits) | (unsigned)d;
                g_rank[b][t] = rank - cum;
            }
            cum += c;
        }
        g_prefix[b][t] = pfx;
        if (last) g_qval[b][t] = key2f(pfx);
    }
    __syncthreads();
    unsigned* hh = &g_hist[0][0][0];
    for (int j = tid; j < BATCH * NQ * 2048; j += blockDim.x) hh[j] = 0u;
}

// ---------------- normalization ----------------
__global__ void k_norm(const float* __restrict__ x, float* __restrict__ xn_out, int use_out) {
    int b = blockIdx.y;
    float* xn = use_out ? xn_out : g_xnorm;
    float q0 = g_qval[b][0], q1 = g_qval[b][1];
    float q2 = g_qval[b][2], q3 = g_qval[b][3];
    float lo = q0 + 0.5f * (q1 - q0);
    float hi = q2 + 0.5f * (q3 - q2);
    float den = hi - lo + EPSV;
    const float4* xi = (const float4*)(x + (size_t)b * HW);
    float4* xo = (float4*)(xn + (size_t)b * HW);
    for (int i = blockIdx.x * blockDim.x + threadIdx.x; i < HW / 4; i += gridDim.x * blockDim.x) {
        float4 v = xi[i];
        float4 o;
        o.x = fminf(fmaxf((v.x - lo) / den, 0.f), 1.f);
        o.y = fminf(fmaxf((v.y - lo) / den, 0.f), 1.f);
        o.z = fminf(fmaxf((v.z - lo) / den, 0.f), 1.f);
        o.w = fminf(fmaxf((v.w - lo) / den, 0.f), 1.f);
        xo[i] = o;
    }
}

// ---------------- fused sobel + orientation + directional scans + end map ----------------
#define TS 32
#define HALO 6
#define SW (TS + 2 * HALO)   // 44
#define SPITCH (SW + 1)      // 45, avoid systematic bank conflicts

__global__ __launch_bounds__(256) void k_fused(const float* __restrict__ xn_in, int use_out,
                                               float* __restrict__ emap,
                                               float* __restrict__ binsf) {
    __shared__ float tile[SW * SPITCH];
    const float* xn = use_out ? xn_in : g_xnorm;
    int b = blockIdx.z;
    int bx = blockIdx.x * TS, by = blockIdx.y * TS;
    const float* xb = xn + (size_t)b * HW;

    for (int i = threadIdx.x; i < SW * SW; i += blockDim.x) {
        int r = i / SW, c = i % SW;
        int gy = by + r - HALO, gx = bx + c - HALO;
        float v = 0.f;
        if ((unsigned)gy < H && (unsigned)gx < W) v = xb[gy * W + gx];
        tile[r * SPITCH + c] = v;
    }
    __syncthreads();

    int lx = threadIdx.x & 31;
    int ly0 = threadIdx.x >> 5;
#pragma unroll
    for (int k = 0; k < 4; k++) {
        int ly = ly0 + k * 8;
        int ty = ly + HALO, tx = lx + HALO;
        const float* t0 = &tile[ty * SPITCH + tx];

        float a00 = t0[-SPITCH - 1], a01 = t0[-SPITCH], a02 = t0[-SPITCH + 1];
        float a10 = t0[-1], a12 = t0[1];
        float a20 = t0[SPITCH - 1], a21 = t0[SPITCH], a22 = t0[SPITCH + 1];
        float gxs = (a02 - a00) + 2.f * (a12 - a10) + (a22 - a20);
        float gys = (a20 - a00) + 2.f * (a21 - a01) + (a22 - a02);

        float ang = atan2f(gys, gxs);
        if (ang < 0.f) ang += TWO_PI_F;
        int bin = (int)floorf(ang / STEP_F);
        bin = min(max(bin, 0), 7);
        int b8 = (bin + 2) & 7;

        int dy = c_dy[b8], dx = c_dx[b8];
        int step = dy * SPITCH + dx;
        float f = 0.f, w = 0.f;
#pragma unroll
        for (int r = 1; r <= 6; r++) {
            f = fmaxf(f, t0[-step * r]);   // forward: x[y - dy*r, x - dx*r]
            w = fmaxf(w, t0[ step * r]);   // backward
        }
        float mn = fminf(f, w), mx = fmaxf(f, w);
        float ratio = mn / (mx + EPSV);
        float x0 = t0[0];
        float em = fminf(fmaxf(x0 * (1.f - ratio), 0.f), 1.f);

        size_t o = (size_t)b * HW + (size_t)(by + ly) * W + (bx + lx);
        emap[o] = em;
        if (binsf) binsf[o] = (float)b8;
    }
}

// ---------------- launch ----------------
extern "C" void kernel_launch(void* const* d_in, const int* in_sizes, int n_in,
                              void* d_out, int out_size) {
    const float* x = (const float*)d_in[0];
    float* out = (float*)d_out;
    const size_t N = (size_t)BATCH * HW;

    float* emap  = out;
    float* binsf = ((size_t)out_size >= 2 * N) ? out + N : nullptr;
    int    use_out_xn = ((size_t)out_size >= 3 * N) ? 1 : 0;
    float* xnout = use_out_xn ? out + 2 * N : nullptr;

    // 1) radix-select quantiles (exact order statistics)
    k_init<<<64, 256>>>();
    {
        dim3 g(128, BATCH);
        k_hist<21, 11, 0><<<g, 256>>>(x);
        k_scan<<<1, 64>>>(11, 1, 0);
        k_hist<10, 11, 11><<<g, 256>>>(x);
        k_scan<<<1, 64>>>(11, 0, 0);
        k_hist<0, 10, 22><<<g, 256>>>(x);
        k_scan<<<1, 64>>>(10, 0, 1);
    }

    // 2) percentile normalization
    {
        dim3 g(128, BATCH);
        k_norm<<<g, 256>>>(x, xnout, use_out_xn);
    }

    // 3) fused sobel + orientation + directional max scans + end map
    {
        dim3 g(W / TS, H / TS, BATCH);
        k_fused<<<g, 256>>>(xnout, use_out_xn, emap, binsf);
    }
}

// round 2
// speedup vs baseline: 2.6653x; 2.6653x over previous
#include <cuda_runtime.h>
#include <math.h>
#include <stdint.h>

#define BATCH 16
#define H 1024
#define W 1024
#define HW (H * W)
#define NQ 4
#define TWO_PI_F 6.28318530717958647692f
#define STEP_F 0.78539816339744830962f
#define EPSV 1e-6f

// ---------------- device scratch ----------------
__device__ unsigned g_hist1[BATCH][2048];
__device__ unsigned g_hist2[BATCH][NQ][2048];
__device__ unsigned g_hist3[BATCH][NQ][1024];
__device__ unsigned g_prefix[BATCH][NQ];
__device__ int      g_rank[BATCH][NQ];
__device__ float    g_qval[BATCH][NQ];

__constant__ int c_dy[8] = {0, -1, -1, -1, 0, 1, 1, 1};
__constant__ int c_dx[8] = {1, 1, 0, -1, -1, -1, 0, 1};

__device__ __forceinline__ unsigned f2key(float f) {
    unsigned u = __float_as_uint(f);
    return (u & 0x80000000u) ? ~u : (u | 0x80000000u);
}
__device__ __forceinline__ float key2f(unsigned k) {
    unsigned u = (k & 0x80000000u) ? (k & 0x7fffffffu) : ~k;
    return __uint_as_float(u);
}

// ---------------- init: zero all histograms, set ranks ----------------
__global__ void k_init() {
    int i = blockIdx.x * blockDim.x + threadIdx.x;
    int stride = gridDim.x * blockDim.x;
    const int T1 = BATCH * 2048;
    const int T2 = BATCH * NQ * 2048;
    const int T3 = BATCH * NQ * 1024;
    unsigned* h1 = &g_hist1[0][0];
    unsigned* h2 = &g_hist2[0][0][0];
    unsigned* h3 = &g_hist3[0][0][0];
    for (int j = i; j < T1; j += stride) h1[j] = 0u;
    for (int j = i; j < T2; j += stride) h2[j] = 0u;
    for (int j = i; j < T3; j += stride) h3[j] = 0u;
    if (i < BATCH * NQ) {
        int b = i / NQ, t = i % NQ;
        const int ranks[NQ] = {20971, 20972, 1027603, 1027604};
        g_rank[b][t] = ranks[t];
        g_prefix[b][t] = 0u;
    }
}

// ---------------- pass 1: histogram of top 11 bits (warp-aggregated) ----------------
__global__ void k_hist1(const float* __restrict__ x) {
    __shared__ unsigned sh[2048];
    int b = blockIdx.y;
    for (int i = threadIdx.x; i < 2048; i += blockDim.x) sh[i] = 0u;
    __syncthreads();

    const float4* xb = (const float4*)(x + (size_t)b * HW);
    const int nvec = HW / 4;
    for (int i = blockIdx.x * blockDim.x + threadIdx.x; i < nvec; i += gridDim.x * blockDim.x) {
        float4 v = xb[i];
        float vs[4] = {v.x, v.y, v.z, v.w};
#pragma unroll
        for (int e = 0; e < 4; e++) {
            unsigned dig = f2key(vs[e]) >> 21;
            unsigned same = __match_any_sync(0xffffffffu, dig);
            if ((int)(threadIdx.x & 31) == __ffs(same) - 1)
                atomicAdd(&sh[dig], (unsigned)__popc(same));
        }
    }
    __syncthreads();
    for (int i = threadIdx.x; i < 2048; i += blockDim.x) {
        unsigned c = sh[i];
        if (c) atomicAdd(&g_hist1[b][i], c);
    }
}

// ---------------- pass 2: refine next 11 bits (predicated, rare matches) ----------------
__global__ void k_hist2(const float* __restrict__ x) {
    __shared__ unsigned sh[NQ][2048];
    __shared__ unsigned spref[NQ];
    int b = blockIdx.y;
    for (int i = threadIdx.x; i < NQ * 2048; i += blockDim.x) ((unsigned*)sh)[i] = 0u;
    if (threadIdx.x < NQ) spref[threadIdx.x] = g_prefix[b][threadIdx.x];
    __syncthreads();
    unsigned p0 = spref[0], p1 = spref[1], p2 = spref[2], p3 = spref[3];

    const float4* xb = (const float4*)(x + (size_t)b * HW);
    const int nvec = HW / 4;
    for (int i = blockIdx.x * blockDim.x + threadIdx.x; i < nvec; i += gridDim.x * blockDim.x) {
        float4 v = xb[i];
        float vs[4] = {v.x, v.y, v.z, v.w};
#pragma unroll
        for (int e = 0; e < 4; e++) {
            unsigned key = f2key(vs[e]);
            unsigned hi = key >> 21;
            unsigned dig = (key >> 10) & 2047u;
            if (hi == p0) atomicAdd(&sh[0][dig], 1u);
            if (hi == p1) atomicAdd(&sh[1][dig], 1u);
            if (hi == p2) atomicAdd(&sh[2][dig], 1u);
            if (hi == p3) atomicAdd(&sh[3][dig], 1u);
        }
    }
    __syncthreads();
    for (int i = threadIdx.x; i < NQ * 2048; i += blockDim.x) {
        unsigned c = ((unsigned*)sh)[i];
        if (c) atomicAdd(&g_hist2[b][i >> 11][i & 2047], c);
    }
}

// ---------------- pass 3: final 10 bits ----------------
__global__ void k_hist3(const float* __restrict__ x) {
    __shared__ unsigned sh[NQ][1024];
    __shared__ unsigned spref[NQ];
    int b = blockIdx.y;
    for (int i = threadIdx.x; i < NQ * 1024; i += blockDim.x) ((unsigned*)sh)[i] = 0u;
    if (threadIdx.x < NQ) spref[threadIdx.x] = g_prefix[b][threadIdx.x];
    __syncthreads();
    unsigned p0 = spref[0], p1 = spref[1], p2 = spref[2], p3 = spref[3];

    const float4* xb = (const float4*)(x + (size_t)b * HW);
    const int nvec = HW / 4;
    for (int i = blockIdx.x * blockDim.x + threadIdx.x; i < nvec; i += gridDim.x * blockDim.x) {
        float4 v = xb[i];
        float vs[4] = {v.x, v.y, v.z, v.w};
#pragma unroll
        for (int e = 0; e < 4; e++) {
            unsigned key = f2key(vs[e]);
            unsigned hi = key >> 10;
            unsigned dig = key & 1023u;
            if (hi == p0) atomicAdd(&sh[0][dig], 1u);
            if (hi == p1) atomicAdd(&sh[1][dig], 1u);
            if (hi == p2) atomicAdd(&sh[2][dig], 1u);
            if (hi == p3) atomicAdd(&sh[3][dig], 1u);
        }
    }
    __syncthreads();
    for (int i = threadIdx.x; i < NQ * 1024; i += blockDim.x) {
        unsigned c = ((unsigned*)sh)[i];
        if (c) atomicAdd(&g_hist3[b][i >> 10][i & 1023], c);
    }
}

// ---------------- scan: one warp per (b,t), shuffle prefix scan ----------------
__global__ void k_scan(int level) {
    int b = blockIdx.x / NQ, t = blockIdx.x % NQ;
    int lane = threadIdx.x;
    const unsigned* h;
    int nb, bits;
    if (level == 1)      { h = g_hist1[b];    nb = 2048; bits = 11; }
    else if (level == 2) { h = g_hist2[b][t]; nb = 2048; bits = 11; }
    else                 { h = g_hist3[b][t]; nb = 1024; bits = 10; }
    int chunk = nb / 32;
    const unsigned* hc = h + lane * chunk;

    unsigned s = 0;
    for (int j = 0; j < chunk; j++) s += hc[j];
    unsigned inc = s;
    for (int o = 1; o < 32; o <<= 1) {
        unsigned v = __shfl_up_sync(0xffffffffu, inc, o);
        if (lane >= o) inc += v;
    }
    unsigned ex = inc - s;  // exclusive prefix
    int rank = g_rank[b][t];
    unsigned ball = __ballot_sync(0xffffffffu, (int)ex <= rank);
    int sel = 31 - __clz(ball);
    if (lane == sel) {
        int r = rank - (int)ex;
        int d = lane * chunk;
        for (int j = 0; j < chunk; j++) {
            unsigned c = hc[j];
            if (r < (int)c) { d = lane * chunk + j; break; }
            r -= (int)c;
        }
        g_rank[b][t] = r;
        unsigned pfx = (g_prefix[b][t] << bits) | (unsigned)d;
        g_prefix[b][t] = pfx;
        if (level == 3) g_qval[b][t] = key2f(pfx);
    }
}

// ---------------- fused: normalize + sobel + orientation + dir-max + end map ----------------
#define TS 32
#define HALO 6
#define SW (TS + 2 * HALO)   // 44
#define SPITCH (SW + 1)      // 45

__global__ __launch_bounds__(256) void k_fused(const float* __restrict__ x,
                                               float* __restrict__ emap,
                                               float* __restrict__ binsf,
                                               float* __restrict__ xnout) {
    __shared__ float tile[SW * SPITCH];
    int b = blockIdx.z;
    int bx = blockIdx.x * TS, by = blockIdx.y * TS;
    const float* xb = x + (size_t)b * HW;

    float q0 = g_qval[b][0], q1 = g_qval[b][1];
    float q2 = g_qval[b][2], q3 = g_qval[b][3];
    float lo = q0 + 0.5f * (q1 - q0);
    float hi = q2 + 0.5f * (q3 - q2);
    float den = hi - lo + EPSV;

    for (int i = threadIdx.x; i < SW * SW; i += blockDim.x) {
        int r = i / SW, c = i % SW;
        int gy = by + r - HALO, gx = bx + c - HALO;
        float v = 0.f;
        if ((unsigned)gy < H && (unsigned)gx < W)
            v = fminf(fmaxf((xb[gy * W + gx] - lo) / den, 0.f), 1.f);
        tile[r * SPITCH + c] = v;
    }
    __syncthreads();

    int lx = threadIdx.x & 31;
    int ly0 = threadIdx.x >> 5;
#pragma unroll
    for (int k = 0; k < 4; k++) {
        int ly = ly0 + k * 8;
        int ty = ly + HALO, tx = lx + HALO;
        const float* t0 = &tile[ty * SPITCH + tx];

        float a00 = t0[-SPITCH - 1], a01 = t0[-SPITCH], a02 = t0[-SPITCH + 1];
        float a10 = t0[-1], a12 = t0[1];
        float a20 = t0[SPITCH - 1], a21 = t0[SPITCH], a22 = t0[SPITCH + 1];
        float gxs = (a02 - a00) + 2.f * (a12 - a10) + (a22 - a20);
        float gys = (a20 - a00) + 2.f * (a21 - a01) + (a22 - a02);

        float ang = atan2f(gys, gxs);
        if (ang < 0.f) ang += TWO_PI_F;
        int bin = (int)floorf(ang / STEP_F);
        bin = min(max(bin, 0), 7);
        int b8 = (bin + 2) & 7;

        int dy = c_dy[b8], dx = c_dx[b8];
        int step = dy * SPITCH + dx;
        float f = 0.f, w = 0.f;
#pragma unroll
        for (int r = 1; r <= 6; r++) {
            f = fmaxf(f, t0[-step * r]);
            w = fmaxf(w, t0[ step * r]);
        }
        float mn = fminf(f, w), mx = fmaxf(f, w);
        float ratio = mn / (mx + EPSV);
        float x0 = t0[0];
        float em = fminf(fmaxf(x0 * (1.f - ratio), 0.f), 1.f);

        size_t o = (size_t)b * HW + (size_t)(by + ly) * W + (bx + lx);
        emap[o] = em;
        if (binsf) binsf[o] = (float)b8;
        if (xnout) xnout[o] = x0;
    }
}

// ---------------- launch ----------------
extern "C" void kernel_launch(void* const* d_in, const int* in_sizes, int n_in,
                              void* d_out, int out_size) {
    const float* x = (const float*)d_in[0];
    float* out = (float*)d_out;
    const size_t N = (size_t)BATCH * HW;

    float* emap  = out;
    float* binsf = ((size_t)out_size >= 2 * N) ? out + N : nullptr;
    float* xnout = ((size_t)out_size >= 3 * N) ? out + 2 * N : nullptr;

    k_init<<<256, 256>>>();
    dim3 g(128, BATCH);
    k_hist1<<<g, 256>>>(x);
    k_scan<<<BATCH * NQ, 32>>>(1);
    k_hist2<<<g, 256>>>(x);
    k_scan<<<BATCH * NQ, 32>>>(2);
    k_hist3<<<g, 256>>>(x);
    k_scan<<<BATCH * NQ, 32>>>(3);

    dim3 gf(W / TS, H / TS, BATCH);
    k_fused<<<gf, 256>>>(x, emap, binsf, xnout);
}